// round 4
// baseline (speedup 1.0000x reference)
#include <cuda_runtime.h>
#include <cuda_bf16.h>
#include <cfloat>
#include <math.h>

#define NN   50000
#define IND  256
#define NHH  4
#define HDD  32
#define NCC  64
#define EMAX 900000
#define SLOPE 0.2f

// ------------------------- scratch (device globals; no allocs allowed) ------
__device__ float g_h[(size_t)NN * 128];        // per-layer transformed features
__device__ float g_act[(size_t)NN * 128];      // elu(prev layer out) = next input
__device__ float g_aggout[(size_t)NN * 128];   // segment-sum output of a layer
__device__ float g_el[NN * NHH];
__device__ float g_er[NN * NHH];
__device__ float g_m[NN * NHH];
__device__ float g_s[NN * NHH];
__device__ float g_sc[(size_t)EMAX * NHH];     // edge scores, then p=exp(e-m)
__device__ float g_alpha[(size_t)EMAX * NHH];
__device__ float g_w[EMAX];
__device__ float g_pseudo[(size_t)NN * NCC];
__device__ float g_agg[(size_t)NN * NCC];
__device__ float g_logits[(size_t)NN * NCC];

// ------------------------------- kernels ------------------------------------
__global__ void k_fill(float* __restrict__ p, float v, int n) {
    int i = blockIdx.x * blockDim.x + threadIdx.x;
    if (i < n) p[i] = v;
}

// y[node, c] = sum_k x[node, k] * W[k, c]   (blockDim.x == M, grid = NN)
__global__ void k_gemm(const float* __restrict__ x, const float* __restrict__ W,
                       float* __restrict__ y, int K, int M) {
    __shared__ float xs[IND];
    int node = blockIdx.x;
    const float* xr = x + (size_t)node * K;
    for (int k = threadIdx.x; k < K; k += M) xs[k] = xr[k];
    __syncthreads();
    int c = threadIdx.x;
    float acc = 0.f;
#pragma unroll 8
    for (int k = 0; k < K; k++) acc = fmaf(xs[k], W[k * M + c], acc);
    y[(size_t)node * M + c] = acc;
}

// el[n,h] = sum_d h[n,h,d]*al[h,d]; er likewise
__global__ void k_elr(const float* __restrict__ h, const float* __restrict__ al,
                      const float* __restrict__ ar, float* __restrict__ el,
                      float* __restrict__ er, int n, int H, int D) {
    int idx = blockIdx.x * blockDim.x + threadIdx.x;
    if (idx >= n * H) return;
    int node = idx / H, hh = idx - node * H;
    const float* hp = h + (size_t)node * H * D + hh * D;
    float a = 0.f, b = 0.f;
#pragma unroll 8
    for (int d = 0; d < D; d++) {
        float v = hp[d];
        a = fmaf(v, al[hh * D + d], a);
        b = fmaf(v, ar[hh * D + d], b);
    }
    el[idx] = a;
    er[idx] = b;
}

__device__ __forceinline__ void atomicMaxF(float* addr, float val) {
    int* ai = (int*)addr;
    int old = *ai;
    while (__int_as_float(old) < val) {
        int assumed = old;
        old = atomicCAS(ai, assumed, __float_as_int(val));
        if (old == assumed) break;
    }
}

__global__ void k_edge_score(const int* __restrict__ src, const int* __restrict__ dst,
                             const float* __restrict__ el, const float* __restrict__ er,
                             float* __restrict__ sc, float* __restrict__ m, int E, int H) {
    int idx = blockIdx.x * blockDim.x + threadIdx.x;
    if (idx >= E * H) return;
    int e = idx / H, hh = idx - e * H;
    float v = el[src[e] * H + hh] + er[dst[e] * H + hh];
    v = v > 0.f ? v : SLOPE * v;
    sc[idx] = v;
    atomicMaxF(&m[dst[e] * H + hh], v);
}

__global__ void k_edge_exp(const int* __restrict__ dst, const float* __restrict__ m,
                           float* __restrict__ sc, float* __restrict__ s, int E, int H) {
    int idx = blockIdx.x * blockDim.x + threadIdx.x;
    if (idx >= E * H) return;
    int e = idx / H, hh = idx - e * H;
    float p = expf(sc[idx] - m[dst[e] * H + hh]);
    sc[idx] = p;
    atomicAdd(&s[dst[e] * H + hh], p);
}

__global__ void k_alpha_w(const int* __restrict__ dst, const float* __restrict__ sc,
                          const float* __restrict__ s, float* __restrict__ alpha,
                          float* __restrict__ w, int E, int H, float wscale) {
    int e = blockIdx.x * blockDim.x + threadIdx.x;
    if (e >= E) return;
    int d = dst[e];
    float acc = 0.f;
    for (int hh = 0; hh < H; hh++) {
        float a = sc[e * H + hh] / (s[d * H + hh] + 1e-9f);
        alpha[e * H + hh] = a;
        acc += a;
    }
    w[e] += acc * wscale;
}

// out[dst, h, d] += alpha[e,h] * h[src, h, d]
__global__ void k_scatter(const int* __restrict__ src, const int* __restrict__ dst,
                          const float* __restrict__ alpha, const float* __restrict__ h,
                          float* __restrict__ out, int E, int H, int D) {
    int HD_ = H * D;
    int idx = blockIdx.x * blockDim.x + threadIdx.x;
    if (idx >= E * HD_) return;
    int e = idx / HD_;
    int hd = idx - e * HD_;
    int hh = hd / D;
    atomicAdd(&out[(size_t)dst[e] * HD_ + hd],
              alpha[e * H + hh] * h[(size_t)src[e] * HD_ + hd]);
}

__global__ void k_elu(const float* __restrict__ in, float* __restrict__ out, int n) {
    int i = blockIdx.x * blockDim.x + threadIdx.x;
    if (i < n) {
        float v = in[i];
        out[i] = v > 0.f ? v : expf(v) - 1.f;
    }
}

// softmax of each 64-wide row (grid=NN, block=64)
__global__ void k_softmax(const float* __restrict__ logits, float* __restrict__ pseudo) {
    __shared__ float red[NCC];
    int node = blockIdx.x, t = threadIdx.x;
    float v = logits[(size_t)node * NCC + t];
    red[t] = v; __syncthreads();
    for (int s = 32; s; s >>= 1) { if (t < s) red[t] = fmaxf(red[t], red[t + s]); __syncthreads(); }
    float mx = red[0]; __syncthreads();
    float ex = expf(v - mx);
    red[t] = ex; __syncthreads();
    for (int s = 32; s; s >>= 1) { if (t < s) red[t] += red[t + s]; __syncthreads(); }
    pseudo[(size_t)node * NCC + t] = ex / red[0];
}

// agg[dst, c] += w[e] * pseudo[src, c]
__global__ void k_lp_scatter(const int* __restrict__ src, const int* __restrict__ dst,
                             const float* __restrict__ w, const float* __restrict__ pseudo,
                             float* __restrict__ agg, int E) {
    int idx = blockIdx.x * blockDim.x + threadIdx.x;
    if (idx >= E * NCC) return;
    int e = idx >> 6;
    int c = idx & 63;
    atomicAdd(&agg[(size_t)dst[e] * NCC + c], w[e] * pseudo[(size_t)src[e] * NCC + c]);
}

// logits = agg @ Wp + bp ; pseudo = softmax(logits)   (grid=NN, block=64)
__global__ void k_linear_softmax(const float* __restrict__ agg, const float* __restrict__ Wp,
                                 const float* __restrict__ bp, float* __restrict__ logits,
                                 float* __restrict__ pseudo) {
    __shared__ float xs[NCC];
    __shared__ float red[NCC];
    int node = blockIdx.x, t = threadIdx.x;
    xs[t] = agg[(size_t)node * NCC + t];
    __syncthreads();
    float v = bp[t];
#pragma unroll 8
    for (int k = 0; k < NCC; k++) v = fmaf(xs[k], Wp[k * NCC + t], v);
    logits[(size_t)node * NCC + t] = v;
    red[t] = v; __syncthreads();
    for (int s = 32; s; s >>= 1) { if (t < s) red[t] = fmaxf(red[t], red[t + s]); __syncthreads(); }
    float mx = red[0]; __syncthreads();
    float ex = expf(v - mx);
    red[t] = ex; __syncthreads();
    for (int s = 32; s; s >>= 1) { if (t < s) red[t] += red[t + s]; __syncthreads(); }
    pseudo[(size_t)node * NCC + t] = ex / red[0];
}

// out = log_softmax(logits)  (== log(pseudo))
__global__ void k_logsoftmax(const float* __restrict__ logits, float* __restrict__ out) {
    __shared__ float red[NCC];
    int node = blockIdx.x, t = threadIdx.x;
    float v = logits[(size_t)node * NCC + t];
    red[t] = v; __syncthreads();
    for (int s = 32; s; s >>= 1) { if (t < s) red[t] = fmaxf(red[t], red[t + s]); __syncthreads(); }
    float mx = red[0]; __syncthreads();
    float ex = expf(v - mx);
    red[t] = ex; __syncthreads();
    for (int s = 32; s; s >>= 1) { if (t < s) red[t] += red[t + s]; __syncthreads(); }
    out[(size_t)node * NCC + t] = (v - mx) - logf(red[0]);
}

// ------------------------------- host driver --------------------------------
static inline int cdiv(long long a, int b) { return (int)((a + b - 1) / b); }

extern "C" void kernel_launch(void* const* d_in, const int* in_sizes, int n_in,
                              void* d_out_v, int out_size) {
    const float* feat = (const float*)d_in[0];
    const int*   src  = (const int*)d_in[1];
    const int*   dst  = (const int*)d_in[2];
    const float* W0   = (const float*)d_in[3];
    const float* al0  = (const float*)d_in[4];
    const float* ar0  = (const float*)d_in[5];
    const float* W1   = (const float*)d_in[6];
    const float* al1  = (const float*)d_in[7];
    const float* ar1  = (const float*)d_in[8];
    const float* W2   = (const float*)d_in[9];
    const float* al2  = (const float*)d_in[10];
    const float* ar2  = (const float*)d_in[11];
    const float* Wp   = (const float*)d_in[12];
    const float* bp   = (const float*)d_in[13];
    float* out = (float*)d_out_v;
    const int E = in_sizes[1];

    float *p_h, *p_act, *p_aggout, *p_el, *p_er, *p_m, *p_s, *p_sc, *p_al,
          *p_w, *p_pseudo, *p_agg, *p_logits;
    cudaGetSymbolAddress((void**)&p_h, g_h);
    cudaGetSymbolAddress((void**)&p_act, g_act);
    cudaGetSymbolAddress((void**)&p_aggout, g_aggout);
    cudaGetSymbolAddress((void**)&p_el, g_el);
    cudaGetSymbolAddress((void**)&p_er, g_er);
    cudaGetSymbolAddress((void**)&p_m, g_m);
    cudaGetSymbolAddress((void**)&p_s, g_s);
    cudaGetSymbolAddress((void**)&p_sc, g_sc);
    cudaGetSymbolAddress((void**)&p_al, g_alpha);
    cudaGetSymbolAddress((void**)&p_w, g_w);
    cudaGetSymbolAddress((void**)&p_pseudo, g_pseudo);
    cudaGetSymbolAddress((void**)&p_agg, g_agg);
    cudaGetSymbolAddress((void**)&p_logits, g_logits);

    k_fill<<<cdiv(E, 256), 256>>>(p_w, 0.f, E);

    // ---------------- layer 0: 256 -> [4, 32] ----------------
    k_gemm<<<NN, 128>>>(feat, W0, p_h, IND, 128);
    k_elr<<<cdiv(NN * 4, 256), 256>>>(p_h, al0, ar0, p_el, p_er, NN, 4, 32);
    k_fill<<<cdiv(NN * 4, 256), 256>>>(p_m, -FLT_MAX, NN * 4);
    k_fill<<<cdiv(NN * 4, 256), 256>>>(p_s, 0.f, NN * 4);
    k_edge_score<<<cdiv((long long)E * 4, 256), 256>>>(src, dst, p_el, p_er, p_sc, p_m, E, 4);
    k_edge_exp<<<cdiv((long long)E * 4, 256), 256>>>(dst, p_m, p_sc, p_s, E, 4);
    k_alpha_w<<<cdiv(E, 256), 256>>>(dst, p_sc, p_s, p_al, p_w, E, 4, 1.f / 12.f);
    k_fill<<<cdiv(NN * 128, 256), 256>>>(p_aggout, 0.f, NN * 128);
    k_scatter<<<cdiv((long long)E * 128, 256), 256>>>(src, dst, p_al, p_h, p_aggout, E, 4, 32);
    k_elu<<<cdiv(NN * 128, 256), 256>>>(p_aggout, p_act, NN * 128);

    // ---------------- layer 1: 128 -> [4, 32] ----------------
    k_gemm<<<NN, 128>>>(p_act, W1, p_h, 128, 128);
    k_elr<<<cdiv(NN * 4, 256), 256>>>(p_h, al1, ar1, p_el, p_er, NN, 4, 32);
    k_fill<<<cdiv(NN * 4, 256), 256>>>(p_m, -FLT_MAX, NN * 4);
    k_fill<<<cdiv(NN * 4, 256), 256>>>(p_s, 0.f, NN * 4);
    k_edge_score<<<cdiv((long long)E * 4, 256), 256>>>(src, dst, p_el, p_er, p_sc, p_m, E, 4);
    k_edge_exp<<<cdiv((long long)E * 4, 256), 256>>>(dst, p_m, p_sc, p_s, E, 4);
    k_alpha_w<<<cdiv(E, 256), 256>>>(dst, p_sc, p_s, p_al, p_w, E, 4, 1.f / 12.f);
    k_fill<<<cdiv(NN * 128, 256), 256>>>(p_aggout, 0.f, NN * 128);
    k_scatter<<<cdiv((long long)E * 128, 256), 256>>>(src, dst, p_al, p_h, p_aggout, E, 4, 32);
    k_elu<<<cdiv(NN * 128, 256), 256>>>(p_aggout, p_act, NN * 128);

    // ---------------- layer 2 (output): 128 -> [1, 64] ----------------
    k_gemm<<<NN, 64>>>(p_act, W2, p_h, 128, 64);
    k_elr<<<cdiv(NN, 256), 256>>>(p_h, al2, ar2, p_el, p_er, NN, 1, 64);
    k_fill<<<cdiv(NN, 256), 256>>>(p_m, -FLT_MAX, NN);
    k_fill<<<cdiv(NN, 256), 256>>>(p_s, 0.f, NN);
    k_edge_score<<<cdiv(E, 256), 256>>>(src, dst, p_el, p_er, p_sc, p_m, E, 1);
    k_edge_exp<<<cdiv(E, 256), 256>>>(dst, p_m, p_sc, p_s, E, 1);
    k_alpha_w<<<cdiv(E, 256), 256>>>(dst, p_sc, p_s, p_al, p_w, E, 1, 1.f / 3.f);
    k_fill<<<cdiv(NN * 64, 256), 256>>>(p_aggout, 0.f, NN * 64);
    k_scatter<<<cdiv((long long)E * 64, 256), 256>>>(src, dst, p_al, p_h, p_aggout, E, 1, 64);
    // logits = p_aggout (mean over 1 head)

    // ---------------- label propagation ----------------
    k_softmax<<<NN, 64>>>(p_aggout, p_pseudo);
    for (int step = 0; step < 10; step++) {
        k_fill<<<cdiv(NN * 64, 256), 256>>>(p_agg, 0.f, NN * 64);
        k_lp_scatter<<<cdiv((long long)E * 64, 256), 256>>>(src, dst, p_w, p_pseudo, p_agg, E);
        k_linear_softmax<<<NN, 64>>>(p_agg, Wp, bp, p_logits, p_pseudo);
    }
    k_logsoftmax<<<NN, 64>>>(p_logits, out);
}

// round 6
// speedup vs baseline: 1.3892x; 1.3892x over previous
#include <cuda_runtime.h>
#include <cuda_bf16.h>
#include <cfloat>
#include <math.h>

#define NN   50000
#define IND  256
#define NCC  64
#define EMAX 900000
#define SLOPE 0.2f

// ------------------------- scratch (device globals) -------------------------
__device__ float g_h[(size_t)NN * 128];      // transformed features (current layer)
__device__ float g_act[(size_t)NN * 128];    // elu output = next layer input
__device__ float g_el[NN * 4];
__device__ float g_er[NN * 4];
__device__ float g_logits[(size_t)NN * NCC]; // GAT output logits
__device__ float g_pseudoA[(size_t)NN * NCC];
__device__ float g_pseudoB[(size_t)NN * NCC];
__device__ int   g_deg[NN];
__device__ int   g_fillc[NN];
__device__ int   g_rowptr[NN + 1];
__device__ int   g_csrc[EMAX];               // CSR (by dst) source node ids
__device__ float g_wcsr[EMAX];               // attention weights in CSR order

// ------------------------------- utility kernels ----------------------------
__global__ void k_fillf(float* __restrict__ p, float v, int n) {
    int i = blockIdx.x * blockDim.x + threadIdx.x;
    if (i < n) p[i] = v;
}
__global__ void k_filli(int* __restrict__ p, int v, int n) {
    int i = blockIdx.x * blockDim.x + threadIdx.x;
    if (i < n) p[i] = v;
}

__global__ void k_hist(const int* __restrict__ dst, int* __restrict__ deg, int E) {
    int e = blockIdx.x * blockDim.x + threadIdx.x;
    if (e < E) atomicAdd(&deg[dst[e]], 1);
}

// one-block exclusive scan over NN degrees -> rowptr[NN+1]
__global__ void k_scan(const int* __restrict__ deg, int* __restrict__ rowptr) {
    const int T = 1024;
    const int TPT = (NN + T - 1) / T;
    __shared__ int part[T];
    int t = threadIdx.x;
    int base = t * TPT;
    int s = 0;
    for (int i = 0; i < TPT; i++) { int idx = base + i; if (idx < NN) s += deg[idx]; }
    part[t] = s; __syncthreads();
    for (int off = 1; off < T; off <<= 1) {
        int v = (t >= off) ? part[t - off] : 0;
        __syncthreads();
        part[t] += v;
        __syncthreads();
    }
    int run = (t == 0) ? 0 : part[t - 1];
    for (int i = 0; i < TPT; i++) {
        int idx = base + i;
        if (idx < NN) { rowptr[idx] = run; run += deg[idx]; }
    }
    if (t == T - 1) rowptr[NN] = part[T - 1];
}

__global__ void k_build_csr(const int* __restrict__ src, const int* __restrict__ dst,
                            const int* __restrict__ rowptr, int* __restrict__ fillc,
                            int* __restrict__ csrc, int E) {
    int e = blockIdx.x * blockDim.x + threadIdx.x;
    if (e >= E) return;
    int d = dst[e];
    int pos = rowptr[d] + atomicAdd(&fillc[d], 1);
    csrc[pos] = src[e];
}

// --------------------------- dense GEMM (node-tiled) ------------------------
// y[node, c] = sum_k x[node, k] * W[k, c]; block = M threads, TN nodes/block
template<int K, int M, int TN>
__global__ void k_gemm_t(const float* __restrict__ x, const float* __restrict__ W,
                         float* __restrict__ y) {
    __shared__ float xs[TN][K];
    int nb = blockIdx.x * TN;
    int c = threadIdx.x;
    for (int idx = threadIdx.x; idx < TN * K; idx += M) {
        int nd = idx / K, k = idx - nd * K;
        int node = nb + nd;
        xs[nd][k] = (node < NN) ? x[(size_t)node * K + k] : 0.f;
    }
    __syncthreads();
    float acc[TN];
#pragma unroll
    for (int i = 0; i < TN; i++) acc[i] = 0.f;
#pragma unroll 4
    for (int k = 0; k < K; k++) {
        float wv = W[k * M + c];
#pragma unroll
        for (int i = 0; i < TN; i++) acc[i] = fmaf(xs[i][k], wv, acc[i]);
    }
#pragma unroll
    for (int i = 0; i < TN; i++) {
        int node = nb + i;
        if (node < NN) y[(size_t)node * M + c] = acc[i];
    }
}

// el[n,h] = sum_d h[n,h,d]*al[h,d]; er likewise
__global__ void k_elr(const float* __restrict__ h, const float* __restrict__ al,
                      const float* __restrict__ ar, float* __restrict__ el,
                      float* __restrict__ er, int H, int D) {
    int idx = blockIdx.x * blockDim.x + threadIdx.x;
    if (idx >= NN * H) return;
    int node = idx / H, hh = idx - node * H;
    const float* hp = h + (size_t)node * H * D + hh * D;
    float a = 0.f, b = 0.f;
#pragma unroll 8
    for (int d = 0; d < D; d++) {
        float v = hp[d];
        a = fmaf(v, al[hh * D + d], a);
        b = fmaf(v, ar[hh * D + d], b);
    }
    el[idx] = a;
    er[idx] = b;
}

// ---------------- fused GAT edge-softmax + aggregation (gather) -------------
// block per node, H*D threads. pass1: warp per head computes max/sum.
// pass2: all threads recompute alpha and accumulate features. w accumulated.
template<int H, int D, bool DO_ELU>
__global__ void k_gat_agg(const int* __restrict__ rowptr, const int* __restrict__ csrc,
                          const float* __restrict__ hf, const float* __restrict__ el,
                          const float* __restrict__ er, float* __restrict__ outp,
                          float* __restrict__ wcsr, float wscale) {
    const int HD = H * D;
    int n = blockIdx.x;
    int t = threadIdx.x;
    int h = t / D, d = t - h * D;
    int rs = rowptr[n], re = rowptr[n + 1];
    __shared__ float sm[H], sinv[H], ser[H];
    if (t < H) ser[t] = er[n * H + t];
    __syncthreads();
    float ernh = ser[h];

    // pass 1: first warp of each D-group computes max then sum for its head
    if (d < 32) {
        float mx = -FLT_MAX;
        for (int j = rs + d; j < re; j += 32) {
            float sc = el[csrc[j] * H + h] + ernh;
            sc = sc > 0.f ? sc : SLOPE * sc;
            mx = fmaxf(mx, sc);
        }
#pragma unroll
        for (int o = 16; o; o >>= 1) mx = fmaxf(mx, __shfl_xor_sync(0xffffffffu, mx, o));
        float sum = 0.f;
        for (int j = rs + d; j < re; j += 32) {
            float sc = el[csrc[j] * H + h] + ernh;
            sc = sc > 0.f ? sc : SLOPE * sc;
            sum += expf(sc - mx);
        }
#pragma unroll
        for (int o = 16; o; o >>= 1) sum += __shfl_xor_sync(0xffffffffu, sum, o);
        if (d == 0) { sm[h] = mx; sinv[h] = 1.f / (sum + 1e-9f); }
    }
    __syncthreads();

    float m_h = sm[h], inv = sinv[h];
    float acc = 0.f;
#pragma unroll 4
    for (int j = rs; j < re; j++) {
        int s_ = csrc[j];
        float sc = el[s_ * H + h] + ernh;
        sc = sc > 0.f ? sc : SLOPE * sc;
        float a = expf(sc - m_h) * inv;
        acc = fmaf(a, hf[(size_t)s_ * HD + t], acc);
        if (d == 0) atomicAdd(&wcsr[j], a * wscale);
    }
    float o = acc;
    if (DO_ELU) o = o > 0.f ? o : expf(o) - 1.f;
    outp[(size_t)n * HD + t] = o;
}

// softmax of each 64-wide row (grid=NN, block=64)
__global__ void k_softmax(const float* __restrict__ logits, float* __restrict__ pseudo) {
    __shared__ float red[NCC];
    int node = blockIdx.x, t = threadIdx.x;
    float v = logits[(size_t)node * NCC + t];
    red[t] = v; __syncthreads();
    for (int s = 32; s; s >>= 1) { if (t < s) red[t] = fmaxf(red[t], red[t + s]); __syncthreads(); }
    float mx = red[0]; __syncthreads();
    float ex = expf(v - mx);
    red[t] = ex; __syncthreads();
    for (int s = 32; s; s >>= 1) { if (t < s) red[t] += red[t + s]; __syncthreads(); }
    pseudo[(size_t)node * NCC + t] = ex / red[0];
}

// ------------- fused label-prop step: gather + linear + softmax -------------
// block per node, 64 threads. pout = softmax(gather@Wp + bp); on last step
// writes log-softmax to outlog instead.
__global__ void k_lp_step(const int* __restrict__ rowptr, const int* __restrict__ csrc,
                          const float* __restrict__ wcsr, const float* __restrict__ pin,
                          const float* __restrict__ Wp, const float* __restrict__ bp,
                          float* __restrict__ pout, float* __restrict__ outlog,
                          int writeLog) {
    __shared__ float xs[NCC];
    __shared__ float red[NCC];
    int n = blockIdx.x, t = threadIdx.x;
    int rs = rowptr[n], re = rowptr[n + 1];
    float acc = 0.f;
#pragma unroll 4
    for (int j = rs; j < re; j++)
        acc = fmaf(wcsr[j], pin[(size_t)csrc[j] * NCC + t], acc);
    xs[t] = acc; __syncthreads();
    float v = bp[t];
#pragma unroll 8
    for (int k = 0; k < NCC; k++) v = fmaf(xs[k], Wp[k * NCC + t], v);
    red[t] = v; __syncthreads();
    for (int s = 32; s; s >>= 1) { if (t < s) red[t] = fmaxf(red[t], red[t + s]); __syncthreads(); }
    float mx = red[0]; __syncthreads();
    float ex = expf(v - mx);
    red[t] = ex; __syncthreads();
    for (int s = 32; s; s >>= 1) { if (t < s) red[t] += red[t + s]; __syncthreads(); }
    float sum = red[0];
    if (writeLog)
        outlog[(size_t)n * NCC + t] = (v - mx) - logf(sum);
    else
        pout[(size_t)n * NCC + t] = ex / sum;
}

// ------------------------------- host driver --------------------------------
static inline int cdiv(long long a, int b) { return (int)((a + b - 1) / b); }

extern "C" void kernel_launch(void* const* d_in, const int* in_sizes, int n_in,
                              void* d_out_v, int out_size) {
    const float* feat = (const float*)d_in[0];
    const int*   src  = (const int*)d_in[1];
    const int*   dst  = (const int*)d_in[2];
    const float* W0   = (const float*)d_in[3];
    const float* al0  = (const float*)d_in[4];
    const float* ar0  = (const float*)d_in[5];
    const float* W1   = (const float*)d_in[6];
    const float* al1  = (const float*)d_in[7];
    const float* ar1  = (const float*)d_in[8];
    const float* W2   = (const float*)d_in[9];
    const float* al2  = (const float*)d_in[10];
    const float* ar2  = (const float*)d_in[11];
    const float* Wp   = (const float*)d_in[12];
    const float* bp   = (const float*)d_in[13];
    float* out = (float*)d_out_v;
    const int E = in_sizes[1];

    float *p_h, *p_act, *p_el, *p_er, *p_logits, *p_pA, *p_pB, *p_w;
    int *p_deg, *p_fill, *p_rp, *p_csrc;
    cudaGetSymbolAddress((void**)&p_h, g_h);
    cudaGetSymbolAddress((void**)&p_act, g_act);
    cudaGetSymbolAddress((void**)&p_el, g_el);
    cudaGetSymbolAddress((void**)&p_er, g_er);
    cudaGetSymbolAddress((void**)&p_logits, g_logits);
    cudaGetSymbolAddress((void**)&p_pA, g_pseudoA);
    cudaGetSymbolAddress((void**)&p_pB, g_pseudoB);
    cudaGetSymbolAddress((void**)&p_w, g_wcsr);
    cudaGetSymbolAddress((void**)&p_deg, g_deg);
    cudaGetSymbolAddress((void**)&p_fill, g_fillc);
    cudaGetSymbolAddress((void**)&p_rp, g_rowptr);
    cudaGetSymbolAddress((void**)&p_csrc, g_csrc);

    // ---- build CSR by dst ----
    k_filli<<<cdiv(NN, 256), 256>>>(p_deg, 0, NN);
    k_filli<<<cdiv(NN, 256), 256>>>(p_fill, 0, NN);
    k_hist<<<cdiv(E, 256), 256>>>(dst, p_deg, E);
    k_scan<<<1, 1024>>>(p_deg, p_rp);
    k_build_csr<<<cdiv(E, 256), 256>>>(src, dst, p_rp, p_fill, p_csrc, E);
    k_fillf<<<cdiv(E, 256), 256>>>(p_w, 0.f, E);

    // ---- layer 0: 256 -> [4,32], ELU ----
    k_gemm_t<IND, 128, 16><<<cdiv(NN, 16), 128>>>(feat, W0, p_h);
    k_elr<<<cdiv(NN * 4, 256), 256>>>(p_h, al0, ar0, p_el, p_er, 4, 32);
    k_gat_agg<4, 32, true><<<NN, 128>>>(p_rp, p_csrc, p_h, p_el, p_er, p_act, p_w, 1.f / 12.f);

    // ---- layer 1: 128 -> [4,32], ELU ----
    k_gemm_t<128, 128, 16><<<cdiv(NN, 16), 128>>>(p_act, W1, p_h);
    k_elr<<<cdiv(NN * 4, 256), 256>>>(p_h, al1, ar1, p_el, p_er, 4, 32);
    k_gat_agg<4, 32, true><<<NN, 128>>>(p_rp, p_csrc, p_h, p_el, p_er, p_act, p_w, 1.f / 12.f);

    // ---- layer 2 (output): 128 -> [1,64] ----
    k_gemm_t<128, 64, 16><<<cdiv(NN, 16), 64>>>(p_act, W2, p_h);
    k_elr<<<cdiv(NN, 256), 256>>>(p_h, al2, ar2, p_el, p_er, 1, 64);
    k_gat_agg<1, 64, false><<<NN, 64>>>(p_rp, p_csrc, p_h, p_el, p_er, p_logits, p_w, 1.f / 3.f);

    // ---- label propagation (10 fused steps, ping-pong) ----
    k_softmax<<<NN, 64>>>(p_logits, p_pA);
    float* pin = p_pA;
    float* pout = p_pB;
    for (int step = 0; step < 10; step++) {
        int last = (step == 9);
        k_lp_step<<<NN, 64>>>(p_rp, p_csrc, p_w, pin, Wp, bp, pout, out, last);
        float* tmp = pin; pin = pout; pout = tmp;
    }
}

// round 8
// speedup vs baseline: 2.7247x; 1.9614x over previous
#include <cuda_runtime.h>
#include <cuda_bf16.h>
#include <cfloat>
#include <math.h>

#define NN   50000
#define IND  256
#define NCC  64
#define EMAX 900000
#define SLOPE 0.2f
#define DMAX 192          // fast-path max in-degree (Poisson(17): P(>192) ~ 0)
#define SCB  256
#define NSCB ((NN + SCB - 1) / SCB)

// ------------------------- scratch (device globals) -------------------------
__device__ float g_h[(size_t)NN * 128];
__device__ float g_act[(size_t)NN * 128];
__device__ float g_el[NN * 4];
__device__ float g_er[NN * 4];
__device__ float g_pseudoA[(size_t)NN * NCC];
__device__ float g_pseudoB[(size_t)NN * NCC];
__device__ int   g_deg[NN];
__device__ int   g_fillc[NN];
__device__ int   g_rowptr[NN + 1];
__device__ int   g_bsum[SCB];
__device__ int   g_boff[SCB];
__device__ int   g_csrc[EMAX];
__device__ float g_wcsr[EMAX];

// ------------------------------- utility ------------------------------------
__global__ void k_fillf(float* __restrict__ p, float v, int n) {
    int i = blockIdx.x * blockDim.x + threadIdx.x;
    if (i < n) p[i] = v;
}
__global__ void k_filli(int* __restrict__ p, int v, int n) {
    int i = blockIdx.x * blockDim.x + threadIdx.x;
    if (i < n) p[i] = v;
}
__global__ void k_hist(const int* __restrict__ dst, int* __restrict__ deg, int E) {
    int e = blockIdx.x * blockDim.x + threadIdx.x;
    if (e < E) atomicAdd(&deg[dst[e]], 1);
}

// ---- decoupled scan: blocksums -> scan blocksums -> per-block scan ----
__global__ void k_scan1(const int* __restrict__ deg, int* __restrict__ bsum) {
    __shared__ int sh[SCB];
    int b = blockIdx.x, t = threadIdx.x;
    int idx = b * SCB + t;
    sh[t] = (idx < NN) ? deg[idx] : 0;
    __syncthreads();
    for (int s = SCB / 2; s; s >>= 1) { if (t < s) sh[t] += sh[t + s]; __syncthreads(); }
    if (t == 0) bsum[b] = sh[0];
}
__global__ void k_scan2(const int* __restrict__ bsum, int* __restrict__ boff) {
    __shared__ int sh[SCB];
    int t = threadIdx.x;
    sh[t] = (t < NSCB) ? bsum[t] : 0;
    __syncthreads();
    for (int o = 1; o < SCB; o <<= 1) {
        int v = (t >= o) ? sh[t - o] : 0;
        __syncthreads(); sh[t] += v; __syncthreads();
    }
    boff[t] = (t == 0) ? 0 : sh[t - 1];
}
__global__ void k_scan3(const int* __restrict__ deg, const int* __restrict__ boff,
                        int* __restrict__ rowptr) {
    __shared__ int sh[SCB];
    int b = blockIdx.x, t = threadIdx.x;
    int idx = b * SCB + t;
    int v = (idx < NN) ? deg[idx] : 0;
    sh[t] = v; __syncthreads();
    for (int o = 1; o < SCB; o <<= 1) {
        int u = (t >= o) ? sh[t - o] : 0;
        __syncthreads(); sh[t] += u; __syncthreads();
    }
    int excl = sh[t] - v + boff[b];
    if (idx < NN) rowptr[idx] = excl;
    if (idx == NN - 1) rowptr[NN] = excl + v;
}

__global__ void k_build_csr(const int* __restrict__ src, const int* __restrict__ dst,
                            const int* __restrict__ rowptr, int* __restrict__ fillc,
                            int* __restrict__ csrc, int E) {
    int e = blockIdx.x * blockDim.x + threadIdx.x;
    if (e >= E) return;
    int d = dst[e];
    int pos = rowptr[d] + atomicAdd(&fillc[d], 1);
    csrc[pos] = src[e];
}

// ------------------ GEMM fused with el/er attention dots --------------------
// y[n,c] = sum_k x[n,k]*W[k,c]; el[n,h] = sum_d y[n,h,d]*al[h,d] (c = h*D+d)
template<int K, int M, int TN, int H>
__global__ void k_gemm_elr(const float* __restrict__ x, const float* __restrict__ W,
                           const float* __restrict__ al, const float* __restrict__ ar,
                           float* __restrict__ y, float* __restrict__ el,
                           float* __restrict__ er) {
    const int NWARP = M / 32;
    const int D = M / H;
    const int WPH = D / 32;
    __shared__ float xs[TN][K];
    __shared__ float spl[TN][NWARP];
    __shared__ float spr[TN][NWARP];
    int nb = blockIdx.x * TN;
    int c = threadIdx.x;
    int warp = c >> 5, lane = c & 31;
    for (int idx = threadIdx.x; idx < TN * K; idx += M) {
        int nd = idx / K, k = idx - nd * K;
        int node = nb + nd;
        xs[nd][k] = (node < NN) ? x[(size_t)node * K + k] : 0.f;
    }
    __syncthreads();
    float acc[TN];
#pragma unroll
    for (int i = 0; i < TN; i++) acc[i] = 0.f;
#pragma unroll 4
    for (int k = 0; k < K; k++) {
        float wv = W[k * M + c];
#pragma unroll
        for (int i = 0; i < TN; i++) acc[i] = fmaf(xs[i][k], wv, acc[i]);
    }
    float alc = al[c], arc = ar[c];
#pragma unroll
    for (int i = 0; i < TN; i++) {
        int node = nb + i;
        if (node < NN) y[(size_t)node * M + c] = acc[i];
        float vl = acc[i] * alc;
        float vr = acc[i] * arc;
#pragma unroll
        for (int o = 16; o; o >>= 1) {
            vl += __shfl_xor_sync(0xffffffffu, vl, o);
            vr += __shfl_xor_sync(0xffffffffu, vr, o);
        }
        if (lane == 0) { spl[i][warp] = vl; spr[i][warp] = vr; }
    }
    __syncthreads();
    if (c < TN * H) {
        int i = c / H, h = c - (c / H) * H;
        float l = 0.f, r = 0.f;
#pragma unroll
        for (int w2 = 0; w2 < WPH; w2++) { l += spl[i][h * WPH + w2]; r += spr[i][h * WPH + w2]; }
        int node = nb + i;
        if (node < NN) { el[node * H + h] = l; er[node * H + h] = r; }
    }
}

// ---------------- fused GAT edge-softmax + aggregation (gather) -------------
// MODE: 0 = ELU epilogue, 2 = row softmax epilogue (requires H*D == 64)
template<int H, int D, int MODE>
__global__ void k_gat_agg(const int* __restrict__ rowptr, const int* __restrict__ csrc,
                          const float* __restrict__ hf, const float* __restrict__ el,
                          const float* __restrict__ er, float* __restrict__ outp,
                          float* __restrict__ wcsr, float wscale) {
    const int HD = H * D;
    __shared__ int   ss[DMAX];
    __shared__ float sal[H][DMAX];
    __shared__ float fsm[H], fsinv[H];
    __shared__ float red[64];
    int n = blockIdx.x;
    int t = threadIdx.x;
    int h = t / D, d = t - h * D;
    int lane = t & 31, warp = t >> 5;
    int rs = rowptr[n];
    int deg = rowptr[n + 1] - rs;
    float ernh = er[n * H + h];
    float acc = 0.f;

    if (deg <= DMAX) {
        for (int j = t; j < deg; j += HD) ss[j] = csrc[rs + j];
        __syncthreads();
        // one warp (d<32) per head: score -> shared, max, exp, sum, normalize
        if (d < 32) {
            float mx = -FLT_MAX;
            for (int j = d; j < deg; j += 32) {
                float sc = el[ss[j] * H + h] + ernh;
                sc = sc > 0.f ? sc : SLOPE * sc;
                sal[h][j] = sc;
                mx = fmaxf(mx, sc);
            }
#pragma unroll
            for (int o = 16; o; o >>= 1) mx = fmaxf(mx, __shfl_xor_sync(0xffffffffu, mx, o));
            float sum = 0.f;
            for (int j = d; j < deg; j += 32) {
                float p = expf(sal[h][j] - mx);
                sal[h][j] = p;
                sum += p;
            }
#pragma unroll
            for (int o = 16; o; o >>= 1) sum += __shfl_xor_sync(0xffffffffu, sum, o);
            float inv = 1.f / (sum + 1e-9f);
            for (int j = d; j < deg; j += 32) sal[h][j] *= inv;
        }
        __syncthreads();
        // warp 0: attention-weight accumulation (plain adds, one owner per slot)
        if (warp == 0) {
            for (int j = lane; j < deg; j += 32) {
                float a = 0.f;
#pragma unroll
                for (int hh = 0; hh < H; hh++) a += sal[hh][j];
                wcsr[rs + j] += a * wscale;
            }
        }
        // feature gather: alpha + src from shared, 4 loads in flight
        float a0_ = 0.f, a1_ = 0.f, a2_ = 0.f, a3_ = 0.f;
        int j = 0;
        for (; j + 4 <= deg; j += 4) {
            int s0 = ss[j], s1 = ss[j + 1], s2 = ss[j + 2], s3 = ss[j + 3];
            float w0 = sal[h][j], w1 = sal[h][j + 1], w2 = sal[h][j + 2], w3 = sal[h][j + 3];
            a0_ = fmaf(w0, hf[(size_t)s0 * HD + t], a0_);
            a1_ = fmaf(w1, hf[(size_t)s1 * HD + t], a1_);
            a2_ = fmaf(w2, hf[(size_t)s2 * HD + t], a2_);
            a3_ = fmaf(w3, hf[(size_t)s3 * HD + t], a3_);
        }
        for (; j < deg; j++) a0_ = fmaf(sal[h][j], hf[(size_t)ss[j] * HD + t], a0_);
        acc = (a0_ + a1_) + (a2_ + a3_);
    } else {
        // slow fallback: recompute scores, atomic w
        if (d < 32) {
            float mx = -FLT_MAX;
            for (int j = rs + d; j < rs + deg; j += 32) {
                float sc = el[csrc[j] * H + h] + ernh;
                sc = sc > 0.f ? sc : SLOPE * sc;
                mx = fmaxf(mx, sc);
            }
#pragma unroll
            for (int o = 16; o; o >>= 1) mx = fmaxf(mx, __shfl_xor_sync(0xffffffffu, mx, o));
            float sum = 0.f;
            for (int j = rs + d; j < rs + deg; j += 32) {
                float sc = el[csrc[j] * H + h] + ernh;
                sc = sc > 0.f ? sc : SLOPE * sc;
                sum += expf(sc - mx);
            }
#pragma unroll
            for (int o = 16; o; o >>= 1) sum += __shfl_xor_sync(0xffffffffu, sum, o);
            if (d == 0) { fsm[h] = mx; fsinv[h] = 1.f / (sum + 1e-9f); }
        }
        __syncthreads();
        float mh = fsm[h], inv = fsinv[h];
        for (int j = rs; j < rs + deg; j++) {
            int s_ = csrc[j];
            float sc = el[s_ * H + h] + ernh;
            sc = sc > 0.f ? sc : SLOPE * sc;
            float a = expf(sc - mh) * inv;
            acc = fmaf(a, hf[(size_t)s_ * HD + t], acc);
            if (d == 0) atomicAdd(&wcsr[j], a * wscale);
        }
    }

    if (MODE == 0) {
        outp[(size_t)n * HD + t] = acc > 0.f ? acc : expf(acc) - 1.f;
    } else { // MODE == 2: softmax over the 64-wide row (HD == 64)
        red[t] = acc; __syncthreads();
        for (int s = 32; s; s >>= 1) { if (t < s) red[t] = fmaxf(red[t], red[t + s]); __syncthreads(); }
        float mx = red[0]; __syncthreads();
        float ex = expf(acc - mx);
        red[t] = ex; __syncthreads();
        for (int s = 32; s; s >>= 1) { if (t < s) red[t] += red[t + s]; __syncthreads(); }
        outp[(size_t)n * HD + t] = ex / red[0];
    }
}

// ------------- fused label-prop step: gather + linear + softmax -------------
__global__ void k_lp_step(const int* __restrict__ rowptr, const int* __restrict__ csrc,
                          const float* __restrict__ wcsr, const float* __restrict__ pin,
                          const float* __restrict__ Wp, const float* __restrict__ bp,
                          float* __restrict__ pout, float* __restrict__ outlog,
                          int writeLog) {
    __shared__ int   ss[DMAX];
    __shared__ float sw[DMAX];
    __shared__ float xs[NCC];
    __shared__ float red[NCC];
    int n = blockIdx.x, t = threadIdx.x;
    int rs = rowptr[n];
    int deg = rowptr[n + 1] - rs;
    float acc0 = 0.f, acc1 = 0.f;
    if (deg <= DMAX) {
        for (int j = t; j < deg; j += NCC) { ss[j] = csrc[rs + j]; sw[j] = wcsr[rs + j]; }
        __syncthreads();
        int j = 0;
        for (; j + 4 <= deg; j += 4) {
            int s0 = ss[j], s1 = ss[j + 1], s2 = ss[j + 2], s3 = ss[j + 3];
            float w0 = sw[j], w1 = sw[j + 1], w2 = sw[j + 2], w3 = sw[j + 3];
            acc0 = fmaf(w0, pin[(size_t)s0 * NCC + t], acc0);
            acc1 = fmaf(w1, pin[(size_t)s1 * NCC + t], acc1);
            acc0 = fmaf(w2, pin[(size_t)s2 * NCC + t], acc0);
            acc1 = fmaf(w3, pin[(size_t)s3 * NCC + t], acc1);
        }
        for (; j < deg; j++) acc0 = fmaf(sw[j], pin[(size_t)ss[j] * NCC + t], acc0);
    } else {
        for (int j = rs; j < rs + deg; j++)
            acc0 = fmaf(wcsr[j], pin[(size_t)csrc[j] * NCC + t], acc0);
    }
    xs[t] = acc0 + acc1; __syncthreads();
    float v = bp[t];
#pragma unroll 8
    for (int k = 0; k < NCC; k++) v = fmaf(xs[k], Wp[k * NCC + t], v);
    red[t] = v; __syncthreads();
    for (int s = 32; s; s >>= 1) { if (t < s) red[t] = fmaxf(red[t], red[t + s]); __syncthreads(); }
    float mx = red[0]; __syncthreads();
    float ex = expf(v - mx);
    red[t] = ex; __syncthreads();
    for (int s = 32; s; s >>= 1) { if (t < s) red[t] += red[t + s]; __syncthreads(); }
    float sum = red[0];
    if (writeLog)
        outlog[(size_t)n * NCC + t] = (v - mx) - logf(sum);
    else
        pout[(size_t)n * NCC + t] = ex / sum;
}

// ------------------------------- host driver --------------------------------
static inline int cdiv(long long a, int b) { return (int)((a + b - 1) / b); }

extern "C" void kernel_launch(void* const* d_in, const int* in_sizes, int n_in,
                              void* d_out_v, int out_size) {
    const float* feat = (const float*)d_in[0];
    const int*   src  = (const int*)d_in[1];
    const int*   dst  = (const int*)d_in[2];
    const float* W0   = (const float*)d_in[3];
    const float* al0  = (const float*)d_in[4];
    const float* ar0  = (const float*)d_in[5];
    const float* W1   = (const float*)d_in[6];
    const float* al1  = (const float*)d_in[7];
    const float* ar1  = (const float*)d_in[8];
    const float* W2   = (const float*)d_in[9];
    const float* al2  = (const float*)d_in[10];
    const float* ar2  = (const float*)d_in[11];
    const float* Wp   = (const float*)d_in[12];
    const float* bp   = (const float*)d_in[13];
    float* out = (float*)d_out_v;
    const int E = in_sizes[1];

    float *p_h, *p_act, *p_el, *p_er, *p_pA, *p_pB, *p_w;
    int *p_deg, *p_fill, *p_rp, *p_csrc, *p_bsum, *p_boff;
    cudaGetSymbolAddress((void**)&p_h, g_h);
    cudaGetSymbolAddress((void**)&p_act, g_act);
    cudaGetSymbolAddress((void**)&p_el, g_el);
    cudaGetSymbolAddress((void**)&p_er, g_er);
    cudaGetSymbolAddress((void**)&p_pA, g_pseudoA);
    cudaGetSymbolAddress((void**)&p_pB, g_pseudoB);
    cudaGetSymbolAddress((void**)&p_w, g_wcsr);
    cudaGetSymbolAddress((void**)&p_deg, g_deg);
    cudaGetSymbolAddress((void**)&p_fill, g_fillc);
    cudaGetSymbolAddress((void**)&p_rp, g_rowptr);
    cudaGetSymbolAddress((void**)&p_csrc, g_csrc);
    cudaGetSymbolAddress((void**)&p_bsum, g_bsum);
    cudaGetSymbolAddress((void**)&p_boff, g_boff);

    // ---- build CSR by dst ----
    k_filli<<<cdiv(NN, 256), 256>>>(p_deg, 0, NN);
    k_filli<<<cdiv(NN, 256), 256>>>(p_fill, 0, NN);
    k_hist<<<cdiv(E, 256), 256>>>(dst, p_deg, E);
    k_scan1<<<NSCB, SCB>>>(p_deg, p_bsum);
    k_scan2<<<1, SCB>>>(p_bsum, p_boff);
    k_scan3<<<NSCB, SCB>>>(p_deg, p_boff, p_rp);
    k_build_csr<<<cdiv(E, 256), 256>>>(src, dst, p_rp, p_fill, p_csrc, E);
    k_fillf<<<cdiv(E, 256), 256>>>(p_w, 0.f, E);

    // ---- layer 0: 256 -> [4,32], ELU ----
    k_gemm_elr<IND, 128, 16, 4><<<cdiv(NN, 16), 128>>>(feat, W0, al0, ar0, p_h, p_el, p_er);
    k_gat_agg<4, 32, 0><<<NN, 128>>>(p_rp, p_csrc, p_h, p_el, p_er, p_act, p_w, 1.f / 12.f);

    // ---- layer 1: 128 -> [4,32], ELU ----
    k_gemm_elr<128, 128, 16, 4><<<cdiv(NN, 16), 128>>>(p_act, W1, al1, ar1, p_h, p_el, p_er);
    k_gat_agg<4, 32, 0><<<NN, 128>>>(p_rp, p_csrc, p_h, p_el, p_er, p_act, p_w, 1.f / 12.f);

    // ---- layer 2 (output): 128 -> [1,64], fused softmax -> pseudo0 ----
    k_gemm_elr<128, 64, 16, 1><<<cdiv(NN, 16), 64>>>(p_act, W2, al2, ar2, p_h, p_el, p_er);
    k_gat_agg<1, 64, 2><<<NN, 64>>>(p_rp, p_csrc, p_h, p_el, p_er, p_pA, p_w, 1.f / 3.f);

    // ---- label propagation (10 fused steps, ping-pong) ----
    float* pin = p_pA;
    float* pout = p_pB;
    for (int step = 0; step < 10; step++) {
        int last = (step == 9);
        k_lp_step<<<NN, 64>>>(p_rp, p_csrc, p_w, pin, Wp, bp, pout, out, last);
        float* tmp = pin; pin = pout; pout = tmp;
    }
}

// round 12
// speedup vs baseline: 3.1277x; 1.1479x over previous
#include <cuda_runtime.h>
#include <cuda_bf16.h>
#include <cfloat>
#include <math.h>

#define NN   50000
#define IND  256
#define NCC  64
#define EMAX 900000
#define SLOPE 0.2f
#define DMAX 192          // gat fast-path max in-degree
#define DLP  96           // lp fast-path max in-degree (Poisson(17): P(>96) ~ 0)
#define NPB  4            // nodes per block in lp_step (NN % NPB == 0)
#define SCB  256
#define NSCB ((NN + SCB - 1) / SCB)

// ------------------------- scratch (device globals) -------------------------
__device__ float g_h[(size_t)NN * 128];
__device__ float g_act[(size_t)NN * 128];
__device__ float g_el[NN * 4];
__device__ float g_er[NN * 4];
__device__ float g_pseudoA[(size_t)NN * NCC];
__device__ float g_pseudoB[(size_t)NN * NCC];
__device__ int   g_deg[NN];
__device__ int   g_fillc[NN];
__device__ int   g_rowptr[NN + 1];
__device__ int   g_bsum[SCB];
__device__ int   g_boff[SCB];
__device__ int   g_csrc[EMAX];
__device__ float g_wcsr[EMAX];

// ------------------------------- utility ------------------------------------
__global__ void k_zero2(int* __restrict__ a, int* __restrict__ b, int n) {
    int i = blockIdx.x * blockDim.x + threadIdx.x;
    if (i < n) { a[i] = 0; b[i] = 0; }
}
__global__ void k_hist(const int* __restrict__ dst, int* __restrict__ deg, int E) {
    int e = blockIdx.x * blockDim.x + threadIdx.x;
    if (e < E) atomicAdd(&deg[dst[e]], 1);
}

// ---- decoupled scan ----
__global__ void k_scan1(const int* __restrict__ deg, int* __restrict__ bsum) {
    __shared__ int sh[SCB];
    int b = blockIdx.x, t = threadIdx.x;
    int idx = b * SCB + t;
    sh[t] = (idx < NN) ? deg[idx] : 0;
    __syncthreads();
    for (int s = SCB / 2; s; s >>= 1) { if (t < s) sh[t] += sh[t + s]; __syncthreads(); }
    if (t == 0) bsum[b] = sh[0];
}
__global__ void k_scan2(const int* __restrict__ bsum, int* __restrict__ boff) {
    __shared__ int sh[SCB];
    int t = threadIdx.x;
    sh[t] = (t < NSCB) ? bsum[t] : 0;
    __syncthreads();
    for (int o = 1; o < SCB; o <<= 1) {
        int v = (t >= o) ? sh[t - o] : 0;
        __syncthreads(); sh[t] += v; __syncthreads();
    }
    boff[t] = (t == 0) ? 0 : sh[t - 1];
}
__global__ void k_scan3(const int* __restrict__ deg, const int* __restrict__ boff,
                        int* __restrict__ rowptr) {
    __shared__ int sh[SCB];
    int b = blockIdx.x, t = threadIdx.x;
    int idx = b * SCB + t;
    int v = (idx < NN) ? deg[idx] : 0;
    sh[t] = v; __syncthreads();
    for (int o = 1; o < SCB; o <<= 1) {
        int u = (t >= o) ? sh[t - o] : 0;
        __syncthreads(); sh[t] += u; __syncthreads();
    }
    int excl = sh[t] - v + boff[b];
    if (idx < NN) rowptr[idx] = excl;
    if (idx == NN - 1) rowptr[NN] = excl + v;
}

__global__ void k_build_csr(const int* __restrict__ src, const int* __restrict__ dst,
                            const int* __restrict__ rowptr, int* __restrict__ fillc,
                            int* __restrict__ csrc, float* __restrict__ wcsr, int E) {
    int e = blockIdx.x * blockDim.x + threadIdx.x;
    if (e >= E) return;
    int d = dst[e];
    int pos = rowptr[d] + atomicAdd(&fillc[d], 1);
    csrc[pos] = src[e];
    wcsr[pos] = 0.f;
}

// ------------------ GEMM fused with el/er attention dots --------------------
template<int K, int M, int TN, int H>
__global__ void k_gemm_elr(const float* __restrict__ x, const float* __restrict__ W,
                           const float* __restrict__ al, const float* __restrict__ ar,
                           float* __restrict__ y, float* __restrict__ el,
                           float* __restrict__ er) {
    const int NWARP = M / 32;
    const int D = M / H;
    const int WPH = D / 32;
    __shared__ float xs[TN][K];
    __shared__ float spl[TN][NWARP];
    __shared__ float spr[TN][NWARP];
    int nb = blockIdx.x * TN;
    int c = threadIdx.x;
    int warp = c >> 5, lane = c & 31;
    for (int idx = threadIdx.x; idx < TN * K; idx += M) {
        int nd = idx / K, k = idx - nd * K;
        int node = nb + nd;
        xs[nd][k] = (node < NN) ? x[(size_t)node * K + k] : 0.f;
    }
    __syncthreads();
    float acc[TN];
#pragma unroll
    for (int i = 0; i < TN; i++) acc[i] = 0.f;
#pragma unroll 4
    for (int k = 0; k < K; k++) {
        float wv = W[k * M + c];
#pragma unroll
        for (int i = 0; i < TN; i++) acc[i] = fmaf(xs[i][k], wv, acc[i]);
    }
    float alc = al[c], arc = ar[c];
#pragma unroll
    for (int i = 0; i < TN; i++) {
        int node = nb + i;
        if (node < NN) y[(size_t)node * M + c] = acc[i];
        float vl = acc[i] * alc;
        float vr = acc[i] * arc;
#pragma unroll
        for (int o = 16; o; o >>= 1) {
            vl += __shfl_xor_sync(0xffffffffu, vl, o);
            vr += __shfl_xor_sync(0xffffffffu, vr, o);
        }
        if (lane == 0) { spl[i][warp] = vl; spr[i][warp] = vr; }
    }
    __syncthreads();
    if (c < TN * H) {
        int i = c / H, h = c - (c / H) * H;
        float l = 0.f, r = 0.f;
#pragma unroll
        for (int w2 = 0; w2 < WPH; w2++) { l += spl[i][h * WPH + w2]; r += spr[i][h * WPH + w2]; }
        int node = nb + i;
        if (node < NN) { el[node * H + h] = l; er[node * H + h] = r; }
    }
}

__device__ __forceinline__ float lrelu(float v) { return v > 0.f ? v : SLOPE * v; }

// ---------------- fused GAT edge-softmax + aggregation (gather) -------------
// MODE: 0 = ELU epilogue, 2 = row softmax epilogue (requires H*D == 64)
template<int H, int D, int MODE>
__global__ void k_gat_agg(const int* __restrict__ rowptr, const int* __restrict__ csrc,
                          const float* __restrict__ hf, const float* __restrict__ el,
                          const float* __restrict__ er, float* __restrict__ outp,
                          float* __restrict__ wcsr, float wscale) {
    const int HD = H * D;
    __shared__ int   ss[DMAX];
    __shared__ float sal[H][DMAX];
    __shared__ float fsm[H], fsinv[H];
    __shared__ float red[64];
    int n = blockIdx.x;
    int t = threadIdx.x;
    int h = t / D, d = t - h * D;
    int lane = t & 31, warp = t >> 5;
    int rs = rowptr[n];
    int deg = rowptr[n + 1] - rs;
    float acc = 0.f;

    if (deg <= DMAX) {
        for (int j = t; j < deg; j += HD) ss[j] = csrc[rs + j];
        __syncthreads();
        if (warp == 0) {
            if (H == 4) {
                // all 4 head scores from one float4 load per edge
                float4 ern = __ldg(&((const float4*)er)[n]);
                float m0 = -FLT_MAX, m1 = -FLT_MAX, m2 = -FLT_MAX, m3 = -FLT_MAX;
                for (int j = lane; j < deg; j += 32) {
                    float4 e = __ldg(&((const float4*)el)[ss[j]]);
                    float s0 = lrelu(e.x + ern.x), s1 = lrelu(e.y + ern.y);
                    float s2 = lrelu(e.z + ern.z), s3 = lrelu(e.w + ern.w);
                    sal[0][j] = s0; sal[1][j] = s1; sal[2][j] = s2; sal[3][j] = s3;
                    m0 = fmaxf(m0, s0); m1 = fmaxf(m1, s1);
                    m2 = fmaxf(m2, s2); m3 = fmaxf(m3, s3);
                }
#pragma unroll
                for (int o = 16; o; o >>= 1) {
                    m0 = fmaxf(m0, __shfl_xor_sync(0xffffffffu, m0, o));
                    m1 = fmaxf(m1, __shfl_xor_sync(0xffffffffu, m1, o));
                    m2 = fmaxf(m2, __shfl_xor_sync(0xffffffffu, m2, o));
                    m3 = fmaxf(m3, __shfl_xor_sync(0xffffffffu, m3, o));
                }
                float u0 = 0.f, u1 = 0.f, u2 = 0.f, u3 = 0.f;
                for (int j = lane; j < deg; j += 32) {
                    float p0 = expf(sal[0][j] - m0), p1 = expf(sal[1][j] - m1);
                    float p2 = expf(sal[2][j] - m2), p3 = expf(sal[3][j] - m3);
                    sal[0][j] = p0; sal[1][j] = p1; sal[2][j] = p2; sal[3][j] = p3;
                    u0 += p0; u1 += p1; u2 += p2; u3 += p3;
                }
#pragma unroll
                for (int o = 16; o; o >>= 1) {
                    u0 += __shfl_xor_sync(0xffffffffu, u0, o);
                    u1 += __shfl_xor_sync(0xffffffffu, u1, o);
                    u2 += __shfl_xor_sync(0xffffffffu, u2, o);
                    u3 += __shfl_xor_sync(0xffffffffu, u3, o);
                }
                float i0 = 1.f / (u0 + 1e-9f), i1 = 1.f / (u1 + 1e-9f);
                float i2 = 1.f / (u2 + 1e-9f), i3 = 1.f / (u3 + 1e-9f);
                for (int j = lane; j < deg; j += 32) {
                    float a0 = sal[0][j] * i0, a1 = sal[1][j] * i1;
                    float a2 = sal[2][j] * i2, a3 = sal[3][j] * i3;
                    sal[0][j] = a0; sal[1][j] = a1; sal[2][j] = a2; sal[3][j] = a3;
                    wcsr[rs + j] += (a0 + a1 + a2 + a3) * wscale;
                }
            } else {
                // H == 1 scalar path
                float ern = __ldg(&er[n]);
                float mx = -FLT_MAX;
                for (int j = lane; j < deg; j += 32) {
                    float sc = lrelu(__ldg(&el[ss[j]]) + ern);
                    sal[0][j] = sc;
                    mx = fmaxf(mx, sc);
                }
#pragma unroll
                for (int o = 16; o; o >>= 1) mx = fmaxf(mx, __shfl_xor_sync(0xffffffffu, mx, o));
                float sum = 0.f;
                for (int j = lane; j < deg; j += 32) {
                    float p = expf(sal[0][j] - mx);
                    sal[0][j] = p; sum += p;
                }
#pragma unroll
                for (int o = 16; o; o >>= 1) sum += __shfl_xor_sync(0xffffffffu, sum, o);
                float inv = 1.f / (sum + 1e-9f);
                for (int j = lane; j < deg; j += 32) {
                    float a = sal[0][j] * inv;
                    sal[0][j] = a;
                    wcsr[rs + j] += a * wscale;
                }
            }
        }
        __syncthreads();
        // feature gather: alpha + src from shared, 8 loads in flight
        float a0_ = 0.f, a1_ = 0.f, a2_ = 0.f, a3_ = 0.f;
        float a4_ = 0.f, a5_ = 0.f, a6_ = 0.f, a7_ = 0.f;
        int j = 0;
        for (; j + 8 <= deg; j += 8) {
            int s0 = ss[j],     s1 = ss[j + 1], s2 = ss[j + 2], s3 = ss[j + 3];
            int s4 = ss[j + 4], s5 = ss[j + 5], s6 = ss[j + 6], s7 = ss[j + 7];
            a0_ = fmaf(sal[h][j],     __ldg(&hf[(size_t)s0 * HD + t]), a0_);
            a1_ = fmaf(sal[h][j + 1], __ldg(&hf[(size_t)s1 * HD + t]), a1_);
            a2_ = fmaf(sal[h][j + 2], __ldg(&hf[(size_t)s2 * HD + t]), a2_);
            a3_ = fmaf(sal[h][j + 3], __ldg(&hf[(size_t)s3 * HD + t]), a3_);
            a4_ = fmaf(sal[h][j + 4], __ldg(&hf[(size_t)s4 * HD + t]), a4_);
            a5_ = fmaf(sal[h][j + 5], __ldg(&hf[(size_t)s5 * HD + t]), a5_);
            a6_ = fmaf(sal[h][j + 6], __ldg(&hf[(size_t)s6 * HD + t]), a6_);
            a7_ = fmaf(sal[h][j + 7], __ldg(&hf[(size_t)s7 * HD + t]), a7_);
        }
        for (; j + 2 <= deg; j += 2) {
            a0_ = fmaf(sal[h][j],     __ldg(&hf[(size_t)ss[j] * HD + t]), a0_);
            a1_ = fmaf(sal[h][j + 1], __ldg(&hf[(size_t)ss[j + 1] * HD + t]), a1_);
        }
        for (; j < deg; j++) a0_ = fmaf(sal[h][j], __ldg(&hf[(size_t)ss[j] * HD + t]), a0_);
        acc = ((a0_ + a1_) + (a2_ + a3_)) + ((a4_ + a5_) + (a6_ + a7_));
    } else {
        // slow fallback: recompute scores, atomic w
        float ernh = er[n * H + h];
        if (d < 32) {
            float mx = -FLT_MAX;
            for (int j = rs + d; j < rs + deg; j += 32)
                mx = fmaxf(mx, lrelu(el[csrc[j] * H + h] + ernh));
#pragma unroll
            for (int o = 16; o; o >>= 1) mx = fmaxf(mx, __shfl_xor_sync(0xffffffffu, mx, o));
            float sum = 0.f;
            for (int j = rs + d; j < rs + deg; j += 32)
                sum += expf(lrelu(el[csrc[j] * H + h] + ernh) - mx);
#pragma unroll
            for (int o = 16; o; o >>= 1) sum += __shfl_xor_sync(0xffffffffu, sum, o);
            if (d == 0) { fsm[h] = mx; fsinv[h] = 1.f / (sum + 1e-9f); }
        }
        __syncthreads();
        float mh = fsm[h], inv = fsinv[h];
        for (int j = rs; j < rs + deg; j++) {
            int s_ = csrc[j];
            float a = expf(lrelu(el[s_ * H + h] + ernh) - mh) * inv;
            acc = fmaf(a, hf[(size_t)s_ * HD + t], acc);
            if (d == 0) atomicAdd(&wcsr[j], a * wscale);
        }
    }

    if (MODE == 0) {
        outp[(size_t)n * HD + t] = acc > 0.f ? acc : expf(acc) - 1.f;
    } else {
        red[t] = acc; __syncthreads();
        for (int s = 32; s; s >>= 1) { if (t < s) red[t] = fmaxf(red[t], red[t + s]); __syncthreads(); }
        float mx = red[0]; __syncthreads();
        float ex = expf(acc - mx);
        red[t] = ex; __syncthreads();
        for (int s = 32; s; s >>= 1) { if (t < s) red[t] += red[t + s]; __syncthreads(); }
        outp[(size_t)n * HD + t] = ex / red[0];
    }
}

// ------- fused label-prop step: 4-node tiled gather + linear + softmax ------
__global__ void k_lp_step(const int* __restrict__ rowptr, const int* __restrict__ csrc,
                          const float* __restrict__ wcsr, const float* __restrict__ pin,
                          const float* __restrict__ Wp, const float* __restrict__ bp,
                          float* __restrict__ pout, float* __restrict__ outlog,
                          int writeLog) {
    __shared__ int   ss[NPB][DLP];
    __shared__ float sw[NPB][DLP];
    __shared__ float xs[NPB][NCC];
    __shared__ float wr[2][NPB];
    int t = threadIdx.x;          // 0..63
    int lane = t & 31, wid = t >> 5;
    int nb = blockIdx.x * NPB;    // NN % NPB == 0
    int rs[NPB], deg[NPB];
    bool fast = true;
#pragma unroll
    for (int i = 0; i < NPB; i++) {
        rs[i] = rowptr[nb + i];
        deg[i] = rowptr[nb + i + 1] - rs[i];
        if (deg[i] > DLP) fast = false;
    }
    float acc[NPB];
#pragma unroll
    for (int i = 0; i < NPB; i++) acc[i] = 0.f;

    if (fast) {
#pragma unroll
        for (int i = 0; i < NPB; i++)
            for (int j = t; j < deg[i]; j += NCC) {
                ss[i][j] = csrc[rs[i] + j];
                sw[i][j] = wcsr[rs[i] + j];
            }
        __syncthreads();
        int dmx = deg[0];
#pragma unroll
        for (int i = 1; i < NPB; i++) dmx = max(dmx, deg[i]);
#pragma unroll 2
        for (int j = 0; j < dmx; j++) {
#pragma unroll
            for (int i = 0; i < NPB; i++) {
                if (j < deg[i])
                    acc[i] = fmaf(sw[i][j], __ldg(&pin[(size_t)ss[i][j] * NCC + t]), acc[i]);
            }
        }
    } else {
#pragma unroll
        for (int i = 0; i < NPB; i++)
            for (int j = rs[i]; j < rs[i] + deg[i]; j++)
                acc[i] = fmaf(wcsr[j], __ldg(&pin[(size_t)csrc[j] * NCC + t]), acc[i]);
        __syncthreads();
    }
#pragma unroll
    for (int i = 0; i < NPB; i++) xs[i][t] = acc[i];
    __syncthreads();

    float v[NPB];
    float b = bp[t];
#pragma unroll
    for (int i = 0; i < NPB; i++) v[i] = b;
#pragma unroll 8
    for (int k = 0; k < NCC; k++) {
        float wv = Wp[k * NCC + t];
#pragma unroll
        for (int i = 0; i < NPB; i++) v[i] = fmaf(xs[i][k], wv, v[i]);
    }

    // concurrent softmax over each node's 64 logits (2-warp reduce)
    float mx[NPB];
#pragma unroll
    for (int i = 0; i < NPB; i++) mx[i] = v[i];
#pragma unroll
    for (int o = 16; o; o >>= 1)
#pragma unroll
        for (int i = 0; i < NPB; i++) mx[i] = fmaxf(mx[i], __shfl_xor_sync(0xffffffffu, mx[i], o));
    if (lane == 0)
#pragma unroll
        for (int i = 0; i < NPB; i++) wr[wid][i] = mx[i];
    __syncthreads();
#pragma unroll
    for (int i = 0; i < NPB; i++) mx[i] = fmaxf(wr[0][i], wr[1][i]);
    __syncthreads();

    float ex[NPB], sm[NPB];
#pragma unroll
    for (int i = 0; i < NPB; i++) { ex[i] = expf(v[i] - mx[i]); sm[i] = ex[i]; }
#pragma unroll
    for (int o = 16; o; o >>= 1)
#pragma unroll
        for (int i = 0; i < NPB; i++) sm[i] += __shfl_xor_sync(0xffffffffu, sm[i], o);
    if (lane == 0)
#pragma unroll
        for (int i = 0; i < NPB; i++) wr[wid][i] = sm[i];
    __syncthreads();
#pragma unroll
    for (int i = 0; i < NPB; i++) sm[i] = wr[0][i] + wr[1][i];

    if (writeLog) {
#pragma unroll
        for (int i = 0; i < NPB; i++)
            outlog[(size_t)(nb + i) * NCC + t] = (v[i] - mx[i]) - logf(sm[i]);
    } else {
#pragma unroll
        for (int i = 0; i < NPB; i++)
            pout[(size_t)(nb + i) * NCC + t] = ex[i] / sm[i];
    }
}

// ------------------------------- host driver --------------------------------
static inline int cdiv(long long a, int b) { return (int)((a + b - 1) / b); }

extern "C" void kernel_launch(void* const* d_in, const int* in_sizes, int n_in,
                              void* d_out_v, int out_size) {
    const float* feat = (const float*)d_in[0];
    const int*   src  = (const int*)d_in[1];
    const int*   dst  = (const int*)d_in[2];
    const float* W0   = (const float*)d_in[3];
    const float* al0  = (const float*)d_in[4];
    const float* ar0  = (const float*)d_in[5];
    const float* W1   = (const float*)d_in[6];
    const float* al1  = (const float*)d_in[7];
    const float* ar1  = (const float*)d_in[8];
    const float* W2   = (const float*)d_in[9];
    const float* al2  = (const float*)d_in[10];
    const float* ar2  = (const float*)d_in[11];
    const float* Wp   = (const float*)d_in[12];
    const float* bp   = (const float*)d_in[13];
    float* out = (float*)d_out_v;
    const int E = in_sizes[1];

    float *p_h, *p_act, *p_el, *p_er, *p_pA, *p_pB, *p_w;
    int *p_deg, *p_fill, *p_rp, *p_csrc, *p_bsum, *p_boff;
    cudaGetSymbolAddress((void**)&p_h, g_h);
    cudaGetSymbolAddress((void**)&p_act, g_act);
    cudaGetSymbolAddress((void**)&p_el, g_el);
    cudaGetSymbolAddress((void**)&p_er, g_er);
    cudaGetSymbolAddress((void**)&p_pA, g_pseudoA);
    cudaGetSymbolAddress((void**)&p_pB, g_pseudoB);
    cudaGetSymbolAddress((void**)&p_w, g_wcsr);
    cudaGetSymbolAddress((void**)&p_deg, g_deg);
    cudaGetSymbolAddress((void**)&p_fill, g_fillc);
    cudaGetSymbolAddress((void**)&p_rp, g_rowptr);
    cudaGetSymbolAddress((void**)&p_csrc, g_csrc);
    cudaGetSymbolAddress((void**)&p_bsum, g_bsum);
    cudaGetSymbolAddress((void**)&p_boff, g_boff);

    // ---- build CSR by dst ----
    k_zero2<<<cdiv(NN, 256), 256>>>(p_deg, p_fill, NN);
    k_hist<<<cdiv(E, 256), 256>>>(dst, p_deg, E);
    k_scan1<<<NSCB, SCB>>>(p_deg, p_bsum);
    k_scan2<<<1, SCB>>>(p_bsum, p_boff);
    k_scan3<<<NSCB, SCB>>>(p_deg, p_boff, p_rp);
    k_build_csr<<<cdiv(E, 256), 256>>>(src, dst, p_rp, p_fill, p_csrc, p_w, E);

    // ---- layer 0: 256 -> [4,32], ELU ----
    k_gemm_elr<IND, 128, 16, 4><<<cdiv(NN, 16), 128>>>(feat, W0, al0, ar0, p_h, p_el, p_er);
    k_gat_agg<4, 32, 0><<<NN, 128>>>(p_rp, p_csrc, p_h, p_el, p_er, p_act, p_w, 1.f / 12.f);

    // ---- layer 1: 128 -> [4,32], ELU ----
    k_gemm_elr<128, 128, 16, 4><<<cdiv(NN, 16), 128>>>(p_act, W1, al1, ar1, p_h, p_el, p_er);
    k_gat_agg<4, 32, 0><<<NN, 128>>>(p_rp, p_csrc, p_h, p_el, p_er, p_act, p_w, 1.f / 12.f);

    // ---- layer 2 (output): 128 -> [1,64], fused softmax -> pseudo0 ----
    k_gemm_elr<128, 64, 16, 1><<<cdiv(NN, 16), 64>>>(p_act, W2, al2, ar2, p_h, p_el, p_er);
    k_gat_agg<1, 64, 2><<<NN, 64>>>(p_rp, p_csrc, p_h, p_el, p_er, p_pA, p_w, 1.f / 3.f);

    // ---- label propagation (10 fused steps, ping-pong) ----
    float* pin = p_pA;
    float* pout = p_pB;
    for (int step = 0; step < 10; step++) {
        int last = (step == 9);
        k_lp_step<<<cdiv(NN, NPB), NCC>>>(p_rp, p_csrc, p_w, pin, Wp, bp, pout, out, last);
        float* tmp = pin; pin = pout; pout = tmp;
    }
}

// round 13
// speedup vs baseline: 3.1620x; 1.0110x over previous
#include <cuda_runtime.h>
#include <cuda_bf16.h>
#include <cfloat>
#include <math.h>

#define NN   50000
#define IND  256
#define NCC  64
#define EMAX 900000
#define SLOPE 0.2f
#define DMAX 192          // gat fast-path max in-degree
#define DLP  96           // lp fast-path max in-degree
#define NPB  4            // nodes per block in lp_step (NN % NPB == 0)
#define SCB  256
#define NSCB ((NN + SCB - 1) / SCB)

// ------------------------- scratch (device globals) -------------------------
__device__ float g_h[(size_t)NN * 128];
__device__ float g_act[(size_t)NN * 128];
__device__ float g_el[NN * 4];
__device__ float g_er[NN * 4];
__device__ float g_pseudoA[(size_t)NN * NCC];
__device__ float g_pseudoB[(size_t)NN * NCC];
__device__ int   g_deg[NN];
__device__ int   g_fillc[NN];
__device__ int   g_rowptr[NN + 1];
__device__ int   g_bsum[SCB];
__device__ int   g_boff[SCB];
__device__ int   g_csrc[EMAX];
__device__ float g_wcsr[EMAX];

// ------------------------------- utility ------------------------------------
__global__ void k_zero2(int* __restrict__ a, int* __restrict__ b, int n) {
    int i = blockIdx.x * blockDim.x + threadIdx.x;
    if (i < n) { a[i] = 0; b[i] = 0; }
}
__global__ void k_hist(const int* __restrict__ dst, int* __restrict__ deg, int E) {
    int e = blockIdx.x * blockDim.x + threadIdx.x;
    if (e < E) atomicAdd(&deg[dst[e]], 1);
}

// ---- decoupled scan ----
__global__ void k_scan1(const int* __restrict__ deg, int* __restrict__ bsum) {
    __shared__ int sh[SCB];
    int b = blockIdx.x, t = threadIdx.x;
    int idx = b * SCB + t;
    sh[t] = (idx < NN) ? deg[idx] : 0;
    __syncthreads();
    for (int s = SCB / 2; s; s >>= 1) { if (t < s) sh[t] += sh[t + s]; __syncthreads(); }
    if (t == 0) bsum[b] = sh[0];
}
__global__ void k_scan2(const int* __restrict__ bsum, int* __restrict__ boff) {
    __shared__ int sh[SCB];
    int t = threadIdx.x;
    sh[t] = (t < NSCB) ? bsum[t] : 0;
    __syncthreads();
    for (int o = 1; o < SCB; o <<= 1) {
        int v = (t >= o) ? sh[t - o] : 0;
        __syncthreads(); sh[t] += v; __syncthreads();
    }
    boff[t] = (t == 0) ? 0 : sh[t - 1];
}
__global__ void k_scan3(const int* __restrict__ deg, const int* __restrict__ boff,
                        int* __restrict__ rowptr) {
    __shared__ int sh[SCB];
    int b = blockIdx.x, t = threadIdx.x;
    int idx = b * SCB + t;
    int v = (idx < NN) ? deg[idx] : 0;
    sh[t] = v; __syncthreads();
    for (int o = 1; o < SCB; o <<= 1) {
        int u = (t >= o) ? sh[t - o] : 0;
        __syncthreads(); sh[t] += u; __syncthreads();
    }
    int excl = sh[t] - v + boff[b];
    if (idx < NN) rowptr[idx] = excl;
    if (idx == NN - 1) rowptr[NN] = excl + v;
}

__global__ void k_build_csr(const int* __restrict__ src, const int* __restrict__ dst,
                            const int* __restrict__ rowptr, int* __restrict__ fillc,
                            int* __restrict__ csrc, float* __restrict__ wcsr, int E) {
    int e = blockIdx.x * blockDim.x + threadIdx.x;
    if (e >= E) return;
    int d = dst[e];
    int pos = rowptr[d] + atomicAdd(&fillc[d], 1);
    csrc[pos] = src[e];
    wcsr[pos] = 0.f;
}

// ------------------ GEMM fused with el/er attention dots --------------------
template<int K, int M, int TN, int H>
__global__ void k_gemm_elr(const float* __restrict__ x, const float* __restrict__ W,
                           const float* __restrict__ al, const float* __restrict__ ar,
                           float* __restrict__ y, float* __restrict__ el,
                           float* __restrict__ er) {
    const int NWARP = M / 32;
    const int D = M / H;
    const int WPH = D / 32;
    __shared__ float xs[TN][K];        // rows K*4 bytes: 16B aligned
    __shared__ float spl[TN][NWARP];
    __shared__ float spr[TN][NWARP];
    int nb = blockIdx.x * TN;
    int c = threadIdx.x;
    int warp = c >> 5, lane = c & 31;
    for (int idx = threadIdx.x; idx < TN * K; idx += M) {
        int nd = idx / K, k = idx - nd * K;
        int node = nb + nd;
        xs[nd][k] = (node < NN) ? x[(size_t)node * K + k] : 0.f;
    }
    __syncthreads();
    float acc[TN];
#pragma unroll
    for (int i = 0; i < TN; i++) acc[i] = 0.f;
    // k-vectorized: float4 shared reads, 4 W loads per 4 k's
    for (int k = 0; k < K; k += 4) {
        float w0 = W[(k + 0) * M + c];
        float w1 = W[(k + 1) * M + c];
        float w2 = W[(k + 2) * M + c];
        float w3 = W[(k + 3) * M + c];
#pragma unroll
        for (int i = 0; i < TN; i++) {
            float4 xv = *reinterpret_cast<const float4*>(&xs[i][k]);
            acc[i] = fmaf(xv.x, w0, acc[i]);
            acc[i] = fmaf(xv.y, w1, acc[i]);
            acc[i] = fmaf(xv.z, w2, acc[i]);
            acc[i] = fmaf(xv.w, w3, acc[i]);
        }
    }
    float alc = al[c], arc = ar[c];
#pragma unroll
    for (int i = 0; i < TN; i++) {
        int node = nb + i;
        if (node < NN) y[(size_t)node * M + c] = acc[i];
        float vl = acc[i] * alc;
        float vr = acc[i] * arc;
#pragma unroll
        for (int o = 16; o; o >>= 1) {
            vl += __shfl_xor_sync(0xffffffffu, vl, o);
            vr += __shfl_xor_sync(0xffffffffu, vr, o);
        }
        if (lane == 0) { spl[i][warp] = vl; spr[i][warp] = vr; }
    }
    __syncthreads();
    if (c < TN * H) {
        int i = c / H, h = c - (c / H) * H;
        float l = 0.f, r = 0.f;
#pragma unroll
        for (int w2_ = 0; w2_ < WPH; w2_++) { l += spl[i][h * WPH + w2_]; r += spr[i][h * WPH + w2_]; }
        int node = nb + i;
        if (node < NN) { el[node * H + h] = l; er[node * H + h] = r; }
    }
}

__device__ __forceinline__ float lrelu(float v) { return v > 0.f ? v : SLOPE * v; }

// ---------------- fused GAT edge-softmax + aggregation (gather) -------------
// MODE: 0 = ELU epilogue, 2 = row softmax epilogue (requires H*D == 64)
template<int H, int D, int MODE>
__global__ void k_gat_agg(const int* __restrict__ rowptr, const int* __restrict__ csrc,
                          const float* __restrict__ hf, const float* __restrict__ el,
                          const float* __restrict__ er, float* __restrict__ outp,
                          float* __restrict__ wcsr, float wscale) {
    const int HD = H * D;
    __shared__ int   ss[DMAX];
    __shared__ float sal[H][DMAX];
    __shared__ float fsm[H], fsinv[H];
    __shared__ float red[64];
    int n = blockIdx.x;
    int t = threadIdx.x;
    int h = t / D, d = t - h * D;
    int lane = t & 31, warp = t >> 5;
    int rs = rowptr[n];
    int deg = rowptr[n + 1] - rs;
    float acc = 0.f;

    if (deg <= DMAX) {
        for (int j = t; j < deg; j += HD) ss[j] = csrc[rs + j];
        __syncthreads();
        if (H == 4) {
            // parallel heads: warp w scores head w (D==32 -> h==warp)
            int w = warp;
            float ernw = __ldg(&er[n * 4 + w]);
            float mxv = -FLT_MAX;
            for (int j = lane; j < deg; j += 32) {
                float sc = lrelu(__ldg(&el[ss[j] * 4 + w]) + ernw);
                sal[w][j] = sc;
                mxv = fmaxf(mxv, sc);
            }
#pragma unroll
            for (int o = 16; o; o >>= 1) mxv = fmaxf(mxv, __shfl_xor_sync(0xffffffffu, mxv, o));
            float sum = 0.f;
            for (int j = lane; j < deg; j += 32) {
                float p = expf(sal[w][j] - mxv);
                sal[w][j] = p;
                sum += p;
            }
#pragma unroll
            for (int o = 16; o; o >>= 1) sum += __shfl_xor_sync(0xffffffffu, sum, o);
            float inv = 1.f / (sum + 1e-9f);
            for (int j = lane; j < deg; j += 32) sal[w][j] *= inv;
            __syncthreads();
            if (warp == 0)
                for (int j = lane; j < deg; j += 32)
                    wcsr[rs + j] += (sal[0][j] + sal[1][j] + sal[2][j] + sal[3][j]) * wscale;
        } else {
            // H == 1 scalar path (warp 0)
            if (warp == 0) {
                float ern = __ldg(&er[n]);
                float mx = -FLT_MAX;
                for (int j = lane; j < deg; j += 32) {
                    float sc = lrelu(__ldg(&el[ss[j]]) + ern);
                    sal[0][j] = sc;
                    mx = fmaxf(mx, sc);
                }
#pragma unroll
                for (int o = 16; o; o >>= 1) mx = fmaxf(mx, __shfl_xor_sync(0xffffffffu, mx, o));
                float sum = 0.f;
                for (int j = lane; j < deg; j += 32) {
                    float p = expf(sal[0][j] - mx);
                    sal[0][j] = p; sum += p;
                }
#pragma unroll
                for (int o = 16; o; o >>= 1) sum += __shfl_xor_sync(0xffffffffu, sum, o);
                float inv = 1.f / (sum + 1e-9f);
                for (int j = lane; j < deg; j += 32) {
                    float a = sal[0][j] * inv;
                    sal[0][j] = a;
                    wcsr[rs + j] += a * wscale;
                }
            }
            __syncthreads();
        }
        // feature gather: alpha + src from shared, 8 loads in flight
        float a0_ = 0.f, a1_ = 0.f, a2_ = 0.f, a3_ = 0.f;
        float a4_ = 0.f, a5_ = 0.f, a6_ = 0.f, a7_ = 0.f;
        int j = 0;
        for (; j + 8 <= deg; j += 8) {
            int s0 = ss[j],     s1 = ss[j + 1], s2 = ss[j + 2], s3 = ss[j + 3];
            int s4 = ss[j + 4], s5 = ss[j + 5], s6 = ss[j + 6], s7 = ss[j + 7];
            a0_ = fmaf(sal[h][j],     __ldg(&hf[(size_t)s0 * HD + t]), a0_);
            a1_ = fmaf(sal[h][j + 1], __ldg(&hf[(size_t)s1 * HD + t]), a1_);
            a2_ = fmaf(sal[h][j + 2], __ldg(&hf[(size_t)s2 * HD + t]), a2_);
            a3_ = fmaf(sal[h][j + 3], __ldg(&hf[(size_t)s3 * HD + t]), a3_);
            a4_ = fmaf(sal[h][j + 4], __ldg(&hf[(size_t)s4 * HD + t]), a4_);
            a5_ = fmaf(sal[h][j + 5], __ldg(&hf[(size_t)s5 * HD + t]), a5_);
            a6_ = fmaf(sal[h][j + 6], __ldg(&hf[(size_t)s6 * HD + t]), a6_);
            a7_ = fmaf(sal[h][j + 7], __ldg(&hf[(size_t)s7 * HD + t]), a7_);
        }
        for (; j + 2 <= deg; j += 2) {
            a0_ = fmaf(sal[h][j],     __ldg(&hf[(size_t)ss[j] * HD + t]), a0_);
            a1_ = fmaf(sal[h][j + 1], __ldg(&hf[(size_t)ss[j + 1] * HD + t]), a1_);
        }
        for (; j < deg; j++) a0_ = fmaf(sal[h][j], __ldg(&hf[(size_t)ss[j] * HD + t]), a0_);
        acc = ((a0_ + a1_) + (a2_ + a3_)) + ((a4_ + a5_) + (a6_ + a7_));
    } else {
        // slow fallback: recompute scores, atomic w
        float ernh = er[n * H + h];
        if (d < 32) {
            float mx = -FLT_MAX;
            for (int j = rs + d; j < rs + deg; j += 32)
                mx = fmaxf(mx, lrelu(el[csrc[j] * H + h] + ernh));
#pragma unroll
            for (int o = 16; o; o >>= 1) mx = fmaxf(mx, __shfl_xor_sync(0xffffffffu, mx, o));
            float sum = 0.f;
            for (int j = rs + d; j < rs + deg; j += 32)
                sum += expf(lrelu(el[csrc[j] * H + h] + ernh) - mx);
#pragma unroll
            for (int o = 16; o; o >>= 1) sum += __shfl_xor_sync(0xffffffffu, sum, o);
            if (d == 0) { fsm[h] = mx; fsinv[h] = 1.f / (sum + 1e-9f); }
        }
        __syncthreads();
        float mh = fsm[h], inv = fsinv[h];
        for (int j = rs; j < rs + deg; j++) {
            int s_ = csrc[j];
            float a = expf(lrelu(el[s_ * H + h] + ernh) - mh) * inv;
            acc = fmaf(a, hf[(size_t)s_ * HD + t], acc);
            if (d == 0) atomicAdd(&wcsr[j], a * wscale);
        }
    }

    if (MODE == 0) {
        outp[(size_t)n * HD + t] = acc > 0.f ? acc : expf(acc) - 1.f;
    } else {
        red[t] = acc; __syncthreads();
        for (int s = 32; s; s >>= 1) { if (t < s) red[t] = fmaxf(red[t], red[t + s]); __syncthreads(); }
        float mx = red[0]; __syncthreads();
        float ex = expf(acc - mx);
        red[t] = ex; __syncthreads();
        for (int s = 32; s; s >>= 1) { if (t < s) red[t] += red[t + s]; __syncthreads(); }
        outp[(size_t)n * HD + t] = ex / red[0];
    }
}

// ------- fused label-prop step: 4-node tiled gather + linear + softmax ------
__global__ void k_lp_step(const int* __restrict__ rowptr, const int* __restrict__ csrc,
                          const float* __restrict__ wcsr, const float* __restrict__ pin,
                          const float* __restrict__ Wp, const float* __restrict__ bp,
                          float* __restrict__ pout, float* __restrict__ outlog,
                          int writeLog) {
    __shared__ int   ss[NPB][DLP];
    __shared__ float sw[NPB][DLP];
    __shared__ float xs[NPB][NCC];   // rows 256B: 16B aligned
    __shared__ float wr[2][NPB];
    int t = threadIdx.x;          // 0..63
    int lane = t & 31, wid = t >> 5;
    int nb = blockIdx.x * NPB;    // NN % NPB == 0
    int rs[NPB], deg[NPB];
    bool fast = true;
#pragma unroll
    for (int i = 0; i < NPB; i++) {
        rs[i] = rowptr[nb + i];
        deg[i] = rowptr[nb + i + 1] - rs[i];
        if (deg[i] > DLP) fast = false;
    }
    float acc[NPB];
#pragma unroll
    for (int i = 0; i < NPB; i++) acc[i] = 0.f;

    if (fast) {
#pragma unroll
        for (int i = 0; i < NPB; i++)
            for (int j = t; j < deg[i]; j += NCC) {
                ss[i][j] = csrc[rs[i] + j];
                sw[i][j] = wcsr[rs[i] + j];
            }
        __syncthreads();
        int dmx = deg[0];
#pragma unroll
        for (int i = 1; i < NPB; i++) dmx = max(dmx, deg[i]);
#pragma unroll 2
        for (int j = 0; j < dmx; j++) {
#pragma unroll
            for (int i = 0; i < NPB; i++) {
                if (j < deg[i])
                    acc[i] = fmaf(sw[i][j], __ldg(&pin[(size_t)ss[i][j] * NCC + t]), acc[i]);
            }
        }
    } else {
#pragma unroll
        for (int i = 0; i < NPB; i++)
            for (int j = rs[i]; j < rs[i] + deg[i]; j++)
                acc[i] = fmaf(wcsr[j], __ldg(&pin[(size_t)csrc[j] * NCC + t]), acc[i]);
        __syncthreads();
    }
#pragma unroll
    for (int i = 0; i < NPB; i++) xs[i][t] = acc[i];
    __syncthreads();

    float v[NPB];
    float b = bp[t];
#pragma unroll
    for (int i = 0; i < NPB; i++) v[i] = b;
    for (int k = 0; k < NCC; k += 4) {
        float w0 = Wp[(k + 0) * NCC + t];
        float w1 = Wp[(k + 1) * NCC + t];
        float w2 = Wp[(k + 2) * NCC + t];
        float w3 = Wp[(k + 3) * NCC + t];
#pragma unroll
        for (int i = 0; i < NPB; i++) {
            float4 xv = *reinterpret_cast<const float4*>(&xs[i][k]);
            v[i] = fmaf(xv.x, w0, v[i]);
            v[i] = fmaf(xv.y, w1, v[i]);
            v[i] = fmaf(xv.z, w2, v[i]);
            v[i] = fmaf(xv.w, w3, v[i]);
        }
    }

    // concurrent softmax over each node's 64 logits (2-warp reduce)
    float mx[NPB];
#pragma unroll
    for (int i = 0; i < NPB; i++) mx[i] = v[i];
#pragma unroll
    for (int o = 16; o; o >>= 1)
#pragma unroll
        for (int i = 0; i < NPB; i++) mx[i] = fmaxf(mx[i], __shfl_xor_sync(0xffffffffu, mx[i], o));
    if (lane == 0)
#pragma unroll
        for (int i = 0; i < NPB; i++) wr[wid][i] = mx[i];
    __syncthreads();
#pragma unroll
    for (int i = 0; i < NPB; i++) mx[i] = fmaxf(wr[0][i], wr[1][i]);
    __syncthreads();

    float ex[NPB], sm[NPB];
#pragma unroll
    for (int i = 0; i < NPB; i++) { ex[i] = expf(v[i] - mx[i]); sm[i] = ex[i]; }
#pragma unroll
    for (int o = 16; o; o >>= 1)
#pragma unroll
        for (int i = 0; i < NPB; i++) sm[i] += __shfl_xor_sync(0xffffffffu, sm[i], o);
    if (lane == 0)
#pragma unroll
        for (int i = 0; i < NPB; i++) wr[wid][i] = sm[i];
    __syncthreads();
#pragma unroll
    for (int i = 0; i < NPB; i++) sm[i] = wr[0][i] + wr[1][i];

    if (writeLog) {
#pragma unroll
        for (int i = 0; i < NPB; i++)
            outlog[(size_t)(nb + i) * NCC + t] = (v[i] - mx[i]) - logf(sm[i]);
    } else {
#pragma unroll
        for (int i = 0; i < NPB; i++)
            pout[(size_t)(nb + i) * NCC + t] = ex[i] / sm[i];
    }
}

// ------------------------------- host driver --------------------------------
static inline int cdiv(long long a, int b) { return (int)((a + b - 1) / b); }

extern "C" void kernel_launch(void* const* d_in, const int* in_sizes, int n_in,
                              void* d_out_v, int out_size) {
    const float* feat = (const float*)d_in[0];
    const int*   src  = (const int*)d_in[1];
    const int*   dst  = (const int*)d_in[2];
    const float* W0   = (const float*)d_in[3];
    const float* al0  = (const float*)d_in[4];
    const float* ar0  = (const float*)d_in[5];
    const float* W1   = (const float*)d_in[6];
    const float* al1  = (const float*)d_in[7];
    const float* ar1  = (const float*)d_in[8];
    const float* W2   = (const float*)d_in[9];
    const float* al2  = (const float*)d_in[10];
    const float* ar2  = (const float*)d_in[11];
    const float* Wp   = (const float*)d_in[12];
    const float* bp   = (const float*)d_in[13];
    float* out = (float*)d_out_v;
    const int E = in_sizes[1];

    float *p_h, *p_act, *p_el, *p_er, *p_pA, *p_pB, *p_w;
    int *p_deg, *p_fill, *p_rp, *p_csrc, *p_bsum, *p_boff;
    cudaGetSymbolAddress((void**)&p_h, g_h);
    cudaGetSymbolAddress((void**)&p_act, g_act);
    cudaGetSymbolAddress((void**)&p_el, g_el);
    cudaGetSymbolAddress((void**)&p_er, g_er);
    cudaGetSymbolAddress((void**)&p_pA, g_pseudoA);
    cudaGetSymbolAddress((void**)&p_pB, g_pseudoB);
    cudaGetSymbolAddress((void**)&p_w, g_wcsr);
    cudaGetSymbolAddress((void**)&p_deg, g_deg);
    cudaGetSymbolAddress((void**)&p_fill, g_fillc);
    cudaGetSymbolAddress((void**)&p_rp, g_rowptr);
    cudaGetSymbolAddress((void**)&p_csrc, g_csrc);
    cudaGetSymbolAddress((void**)&p_bsum, g_bsum);
    cudaGetSymbolAddress((void**)&p_boff, g_boff);

    // ---- build CSR by dst ----
    k_zero2<<<cdiv(NN, 256), 256>>>(p_deg, p_fill, NN);
    k_hist<<<cdiv(E, 256), 256>>>(dst, p_deg, E);
    k_scan1<<<NSCB, SCB>>>(p_deg, p_bsum);
    k_scan2<<<1, SCB>>>(p_bsum, p_boff);
    k_scan3<<<NSCB, SCB>>>(p_deg, p_boff, p_rp);
    k_build_csr<<<cdiv(E, 256), 256>>>(src, dst, p_rp, p_fill, p_csrc, p_w, E);

    // ---- layer 0: 256 -> [4,32], ELU ----
    k_gemm_elr<IND, 128, 16, 4><<<cdiv(NN, 16), 128>>>(feat, W0, al0, ar0, p_h, p_el, p_er);
    k_gat_agg<4, 32, 0><<<NN, 128>>>(p_rp, p_csrc, p_h, p_el, p_er, p_act, p_w, 1.f / 12.f);

    // ---- layer 1: 128 -> [4,32], ELU ----
    k_gemm_elr<128, 128, 16, 4><<<cdiv(NN, 16), 128>>>(p_act, W1, al1, ar1, p_h, p_el, p_er);
    k_gat_agg<4, 32, 0><<<NN, 128>>>(p_rp, p_csrc, p_h, p_el, p_er, p_act, p_w, 1.f / 12.f);

    // ---- layer 2 (output): 128 -> [1,64], fused softmax -> pseudo0 ----
    k_gemm_elr<128, 64, 16, 1><<<cdiv(NN, 16), 64>>>(p_act, W2, al2, ar2, p_h, p_el, p_er);
    k_gat_agg<1, 64, 2><<<NN, 64>>>(p_rp, p_csrc, p_h, p_el, p_er, p_pA, p_w, 1.f / 3.f);

    // ---- label propagation (10 fused steps, ping-pong) ----
    float* pin = p_pA;
    float* pout = p_pB;
    for (int step = 0; step < 10; step++) {
        int last = (step == 9);
        k_lp_step<<<cdiv(NN, NPB), NCC>>>(p_rp, p_csrc, p_w, pin, Wp, bp, pout, out, last);
        float* tmp = pin; pin = pout; pout = tmp;
    }
}